// round 7
// baseline (speedup 1.0000x reference)
#include <cuda_runtime.h>
#include <cstdint>

// ---------------------------------------------------------------------------
// T2FN: fusion = sum_t (a1 ⊗ v1 ⊗ x1)  [B, 49*49*97], then 3-layer MLP.
// Stage 1: materialize fusion (fp32, row-padded) via smem-staged outer GEMM.
// Stage 2: split-K GEMM fusion[128,FD] @ W1[FD,128] -> 296 partials.
//          A-tile loaded vectorized along f, transposed into smem.
//          As row stride = 132 floats (528 B, 16B-multiple) so LDS.128 reads
//          are aligned; the 4-way STS conflict on the transpose is hidden
//          behind the FFMA2 issue floor (512 vs 4096 cyc/CTA-tile).
// Stage 3: reduce partials + bias/relu + h1@W2 relu + h2@W3 sigmoid*6-3.
// Inner loops use packed fma.rn.f32x2 (Blackwell FFMA2).
// ---------------------------------------------------------------------------

typedef unsigned long long u64;

constexpr int B_  = 128;
constexpr int T_  = 64;
constexpr int A_  = 48;
constexpr int V_  = 48;
constexpr int X_  = 96;
constexpr int AI  = A_ + 1;      // 49
constexpr int VJ  = V_ + 1;      // 49
constexpr int XK  = X_ + 1;      // 97
constexpr int IJ  = AI * VJ;     // 2401
constexpr int FD  = IJ * XK;     // 232897
constexpr int FDP = 232928;      // FD padded to multiple of 32 (= 7279*32)
constexpr int PF  = 128;
constexpr int NSPLIT = 296;      // split-K CTAs for the big GEMM
constexpr int KT  = 32;          // GEMM K-tile
constexpr int NTILES = FDP / KT; // 7279

// scratch (static device allocations are allowed; zero-initialized, and the
// pad region [FD, FDP) of each row is never written -> stays zero)
__device__ float g_fusion[(size_t)B_ * FDP];         // ~119 MB
__device__ float g_part[(size_t)NSPLIT * B_ * PF];   // ~19.4 MB

__device__ __forceinline__ u64 pack2(float lo, float hi) {
    u64 r;
    asm("mov.b64 %0, {%1, %2};" : "=l"(r) : "f"(lo), "f"(hi));
    return r;
}
__device__ __forceinline__ void fma2(u64& acc, u64 a, u64 b) {
    asm("fma.rn.f32x2 %0, %1, %2, %0;" : "+l"(acc) : "l"(a), "l"(b));
}
__device__ __forceinline__ void unpack2(u64 v, float& lo, float& hi) {
    lo = __uint_as_float((unsigned)(v & 0xffffffffull));
    hi = __uint_as_float((unsigned)(v >> 32));
}

// ---------------------------------------------------------------------------
// Stage 1: fusion formation.
// grid = (ij_tiles=10, k_tiles=2, b=128), 256 threads, 2 CTAs/SM.
// CTA computes a [256 ij x 64 k] tile of fusion[b] = sum_t av[ij,t]*x1[t,k].
// a/v staged in smem ONCE (with ones column), x staged per 16-t chunk,
// av built from LDS (no strided LDG), 8x8 register micro-tiles with FFMA2.
// ---------------------------------------------------------------------------
__global__ void __launch_bounds__(256, 2)
fusion_kernel(const float* __restrict__ audio,
              const float* __restrict__ video,
              const float* __restrict__ text)
{
    __shared__ float a_s[T_][AI];                 // 12.25 KB (col 0 = 1)
    __shared__ float v_s[T_][VJ];                 // 12.25 KB
    __shared__ __align__(16) float xs[16][64];    //  4 KB (per t-chunk)
    __shared__ __align__(16) float av_s[16][260]; // 16.25 KB (row = 65*16B)

    const int b      = blockIdx.z;
    const int ijbase = blockIdx.x * 256;
    const int kbase  = blockIdx.y * 64;
    const int tid    = threadIdx.x;
    const int tr     = tid >> 3;   // 0..31 -> ij micro-rows (8 each)
    const int tc     = tid & 7;    // 0..7  -> k  micro-cols (8 each)

    // ---- stage a_s / v_s (ones column + coalesced body loads) ----
    if (tid < T_) { a_s[tid][0] = 1.f; v_s[tid][0] = 1.f; }
    {
        const float* ab = audio + (size_t)b * T_ * A_;
        const float* vb = video + (size_t)b * T_ * V_;
        for (int idx = tid; idx < T_ * A_; idx += 256) {
            const int t = idx / A_;
            const int c = idx - t * A_;
            a_s[t][c + 1] = ab[idx];
            v_s[t][c + 1] = vb[idx];
        }
    }

    // per-thread ij identity (for av build)
    const int  ij   = ijbase + tid;
    const bool ijok = (ij < IJ);
    const int  ii   = ijok ? (ij / VJ) : 0;
    const int  jj   = ijok ? (ij - ii * VJ) : 0;

    u64 acc[8][4];
#pragma unroll
    for (int i = 0; i < 8; i++)
#pragma unroll
        for (int j = 0; j < 4; j++) acc[i][j] = 0ull;

    __syncthreads();

    for (int t0 = 0; t0 < T_; t0 += 16) {
        // stage x tile for this chunk (coalesced; k==0 -> ones, k>=XK -> 0)
        for (int idx = tid; idx < 16 * 64; idx += 256) {
            const int tt = idx >> 6;
            const int kk = idx & 63;
            const int k  = kbase + kk;
            float xv = 0.f;
            if (k == 0)      xv = 1.f;
            else if (k < XK) xv = text[(size_t)(b * T_ + t0 + tt) * X_ + (k - 1)];
            xs[tt][kk] = xv;
        }
        // build av column for this thread's ij (pure LDS)
#pragma unroll 4
        for (int tt = 0; tt < 16; tt++) {
            const int t = t0 + tt;
            av_s[tt][tid] = ijok ? a_s[t][ii] * v_s[t][jj] : 0.f;
        }
        __syncthreads();

#pragma unroll 4
        for (int tt = 0; tt < 16; tt++) {
            const float4 a0 = *(const float4*)&av_s[tt][tr * 8];
            const float4 a1 = *(const float4*)&av_s[tt][tr * 8 + 4];
            const ulonglong2 xA = *(const ulonglong2*)&xs[tt][tc * 8];
            const ulonglong2 xB = *(const ulonglong2*)&xs[tt][tc * 8 + 4];
            const float aa[8] = {a0.x, a0.y, a0.z, a0.w, a1.x, a1.y, a1.z, a1.w};
#pragma unroll
            for (int i = 0; i < 8; i++) {
                const u64 ad = pack2(aa[i], aa[i]);
                fma2(acc[i][0], ad, xA.x);
                fma2(acc[i][1], ad, xA.y);
                fma2(acc[i][2], ad, xB.x);
                fma2(acc[i][3], ad, xB.y);
            }
        }
        __syncthreads();
    }

    // store this thread's 8x8 micro-tile
#pragma unroll
    for (int i = 0; i < 8; i++) {
        const int oij = ijbase + tr * 8 + i;
        if (oij >= IJ) continue;
        float* dst = g_fusion + (size_t)b * FDP + (size_t)oij * XK;
#pragma unroll
        for (int j = 0; j < 4; j++) {
            const int k = kbase + tc * 8 + j * 2;
            float lo, hi;
            unpack2(acc[i][j], lo, hi);
            if (k     < XK) dst[k]     = lo;
            if (k + 1 < XK) dst[k + 1] = hi;
        }
    }
}

// ---------------------------------------------------------------------------
// Stage 2: h1_pre partials. Split-K GEMM: [128 x FDP] @ [FDP x 128].
// 296 CTAs; 256 threads; KT=32. A loaded as float4 along f (coalesced, 4
// lines/warp-LDG) and transposed to As[kk][b] (stride 132: 528 B rows keep
// every LDS.128 16B-aligned; STS conflicts hidden behind FFMA2 issue).
// B loaded float4 -> STS.128. 8x8 micro-tiles, FFMA2.
// ---------------------------------------------------------------------------
__global__ void __launch_bounds__(256, 2)
gemm_kernel(const float* __restrict__ W1)
{
    __shared__ __align__(16) float As[KT][132];  // [kk][b]  16.5 KB
    __shared__ __align__(16) float Bs[KT][132];  // [kk][p]  16.5 KB

    const int tid = threadIdx.x;
    const int tr  = tid >> 4;   // 0..15 -> b rows tr*8..+7
    const int tc  = tid & 15;   // 0..15 -> p cols tc*8..+7

    // A-load mapping: lanes along f
    const int a_f4   = tid & 7;        // float4 index within 32-float row
    const int a_brow = tid >> 3;       // 0..31
    // B-load mapping
    const int b_p4 = tid & 31;
    const int b_kk = tid >> 5;         // 0..7

    u64 acc[8][4];
#pragma unroll
    for (int i = 0; i < 8; i++)
#pragma unroll
        for (int j = 0; j < 4; j++) acc[i][j] = 0ull;

    for (int tile = blockIdx.x; tile < NTILES; tile += NSPLIT) {
        const int kb = tile * KT;

        // A-tile: read float4 along f, transpose into As[kk][b]
#pragma unroll
        for (int u = 0; u < 4; u++) {
            const int b = a_brow + u * 32;
            const float4 va =
                *(const float4*)(g_fusion + (size_t)b * FDP + kb + a_f4 * 4);
            As[a_f4 * 4 + 0][b] = va.x;
            As[a_f4 * 4 + 1][b] = va.y;
            As[a_f4 * 4 + 2][b] = va.z;
            As[a_f4 * 4 + 3][b] = va.w;
        }
        // B-tile: coalesced float4, direct
#pragma unroll
        for (int u = 0; u < 4; u++) {
            const int kk = b_kk + u * 8;
            const int f  = kb + kk;
            float4 vb = make_float4(0.f, 0.f, 0.f, 0.f);
            if (f < FD) vb = *(const float4*)(W1 + (size_t)f * PF + b_p4 * 4);
            *(float4*)&Bs[kk][b_p4 * 4] = vb;
        }
        __syncthreads();

#pragma unroll
        for (int kk = 0; kk < KT; kk++) {
            const float4 a0 = *(const float4*)&As[kk][tr * 8];
            const float4 a1 = *(const float4*)&As[kk][tr * 8 + 4];
            const ulonglong2 bA = *(const ulonglong2*)&Bs[kk][tc * 8];
            const ulonglong2 bB = *(const ulonglong2*)&Bs[kk][tc * 8 + 4];
            const float aa[8] = {a0.x, a0.y, a0.z, a0.w, a1.x, a1.y, a1.z, a1.w};
#pragma unroll
            for (int i = 0; i < 8; i++) {
                const u64 ad = pack2(aa[i], aa[i]);
                fma2(acc[i][0], ad, bA.x);
                fma2(acc[i][1], ad, bA.y);
                fma2(acc[i][2], ad, bB.x);
                fma2(acc[i][3], ad, bB.y);
            }
        }
        __syncthreads();
    }

    // deterministic partial store
    float* base = g_part + (size_t)blockIdx.x * B_ * PF;
#pragma unroll
    for (int i = 0; i < 8; i++) {
        const int b = tr * 8 + i;
        u64* row = (u64*)(base + (size_t)b * PF + tc * 8);
#pragma unroll
        for (int j = 0; j < 4; j++) row[j] = acc[i][j];
    }
}

// ---------------------------------------------------------------------------
// Stage 3: reduce partials -> h1 (relu) -> h2 (relu) -> sigmoid*6-3.
// ---------------------------------------------------------------------------
__global__ void __launch_bounds__(128)
mlp_kernel(const float* __restrict__ b1,
           const float* __restrict__ W2,
           const float* __restrict__ b2,
           const float* __restrict__ W3,
           const float* __restrict__ b3,
           float* __restrict__ out)
{
    __shared__ float h1[128];
    __shared__ float red[128];
    const int b = blockIdx.x;
    const int p = threadIdx.x;

    float s = b1[p];
    const float* pp = g_part + (size_t)b * PF + p;
#pragma unroll 8
    for (int c = 0; c < NSPLIT; c++) s += pp[(size_t)c * B_ * PF];
    h1[p] = fmaxf(s, 0.f);
    __syncthreads();

    float s2 = b2[p];
#pragma unroll 8
    for (int q = 0; q < PF; q++) s2 = fmaf(h1[q], W2[q * PF + p], s2);
    const float h2 = fmaxf(s2, 0.f);

    red[p] = h2 * W3[p];
    __syncthreads();
    for (int st = 64; st > 0; st >>= 1) {
        if (p < st) red[p] += red[p + st];
        __syncthreads();
    }
    if (p == 0) {
        const float z = red[0] + b3[0];
        out[b] = 6.f / (1.f + expf(-z)) - 3.f;
    }
}

// ---------------------------------------------------------------------------
extern "C" void kernel_launch(void* const* d_in, const int* in_sizes, int n_in,
                              void* d_out, int out_size)
{
    const float* audio = (const float*)d_in[0];
    const float* video = (const float*)d_in[1];
    const float* text  = (const float*)d_in[2];
    const float* W1    = (const float*)d_in[3];
    const float* b1    = (const float*)d_in[4];
    const float* W2    = (const float*)d_in[5];
    const float* b2    = (const float*)d_in[6];
    const float* W3    = (const float*)d_in[7];
    const float* b3    = (const float*)d_in[8];

    fusion_kernel<<<dim3((IJ + 255) / 256, 2, B_), 256>>>(audio, video, text);
    gemm_kernel<<<NSPLIT, 256>>>(W1);
    mlp_kernel<<<B_, 128>>>(b1, W2, b2, W3, b3, (float*)d_out);
}

// round 9
// speedup vs baseline: 1.8103x; 1.8103x over previous
#include <cuda_runtime.h>
#include <cstdint>

// ---------------------------------------------------------------------------
// T2FN: fusion = sum_t (a1 ⊗ v1 ⊗ x1)  [B, 49*49*97], then 3-layer MLP.
// Stage 1 (fusion): 512-thr CTAs, 4ij x 8k per-thread tiles (acc 32 regs ->
//   2 CTAs/SM = 32 warps), bank-conflict-free smem reads (k split tc*4/+32).
// Stage 2 (gemm):   split-K 296 CTAs, 256 thr, 8b x 8p tiles with p split
//   tc*4/+64 (Bs reads at the 2-wavefront minimum), register prefetch of the
//   next K-tile to hide gmem latency.
// Stage 3 (mlp):    reduce partials + bias/relu chain + sigmoid*6-3.
// Inner loops use packed fma.rn.f32x2 (Blackwell FFMA2).
// ---------------------------------------------------------------------------

typedef unsigned long long u64;

constexpr int B_  = 128;
constexpr int T_  = 64;
constexpr int A_  = 48;
constexpr int V_  = 48;
constexpr int X_  = 96;
constexpr int AI  = A_ + 1;      // 49
constexpr int VJ  = V_ + 1;      // 49
constexpr int XK  = X_ + 1;      // 97
constexpr int IJ  = AI * VJ;     // 2401
constexpr int FD  = IJ * XK;     // 232897
constexpr int FDP = 232928;      // FD padded to multiple of 32
constexpr int PF  = 128;
constexpr int NSPLIT = 296;      // split-K CTAs (2 waves-exact on 148 SMs)
constexpr int KT  = 32;          // GEMM K-tile
constexpr int NTILES = FDP / KT; // 7279

__device__ float g_fusion[(size_t)B_ * FDP];         // ~119 MB
__device__ float g_part[(size_t)NSPLIT * B_ * PF];   // ~19.4 MB

__device__ __forceinline__ u64 pack2(float lo, float hi) {
    u64 r;
    asm("mov.b64 %0, {%1, %2};" : "=l"(r) : "f"(lo), "f"(hi));
    return r;
}
__device__ __forceinline__ void fma2(u64& acc, u64 a, u64 b) {
    asm("fma.rn.f32x2 %0, %1, %2, %0;" : "+l"(acc) : "l"(a), "l"(b));
}
__device__ __forceinline__ void unpack2(u64 v, float& lo, float& hi) {
    lo = __uint_as_float((unsigned)(v & 0xffffffffull));
    hi = __uint_as_float((unsigned)(v >> 32));
}

// ---------------------------------------------------------------------------
// Stage 1: fusion formation. grid = (10 ij-tiles, 2 k-tiles, 128 b).
// 512 threads; CTA tile 256 ij x 64 k; per-thread 4 ij x 8 k.
// ---------------------------------------------------------------------------
__global__ void __launch_bounds__(512, 2)
fusion_kernel(const float* __restrict__ audio,
              const float* __restrict__ video,
              const float* __restrict__ text)
{
    __shared__ float a_s[T_][AI];                 // 12.25 KB (col 0 = 1)
    __shared__ float v_s[T_][VJ];                 // 12.25 KB
    __shared__ __align__(16) float xs[16][64];    //  4 KB
    __shared__ __align__(16) float av_s[16][260]; // 16.25 KB (row 65*16B)

    const int b      = blockIdx.z;
    const int ijbase = blockIdx.x * 256;
    const int kbase  = blockIdx.y * 64;
    const int tid    = threadIdx.x;
    const int tr     = tid >> 3;   // 0..63 -> ij rows tr*4..+3
    const int tc     = tid & 7;    // 0..7  -> k cols {tc*4..+3, tc*4+32..+35}

    // ---- stage a_s / v_s (ones column + coalesced body loads) ----
    if (tid < T_) { a_s[tid][0] = 1.f; v_s[tid][0] = 1.f; }
    {
        const float* ab = audio + (size_t)b * T_ * A_;
        const float* vb = video + (size_t)b * T_ * V_;
        for (int idx = tid; idx < T_ * A_; idx += 512) {
            const int t = idx / A_;
            const int c = idx - t * A_;
            a_s[t][c + 1] = ab[idx];
            v_s[t][c + 1] = vb[idx];
        }
    }

    // av-build identity: this thread fills (tt = ttbase+2u, ijcol) entries
    const int  ijcol = tid & 255;
    const int  ttbase = tid >> 8;          // 0 or 1
    const int  ij   = ijbase + ijcol;
    const bool ijok = (ij < IJ);
    const int  ii   = ijok ? (ij / VJ) : 0;
    const int  jj   = ijok ? (ij - ii * VJ) : 0;

    u64 acc[4][4];
#pragma unroll
    for (int i = 0; i < 4; i++)
#pragma unroll
        for (int j = 0; j < 4; j++) acc[i][j] = 0ull;

    __syncthreads();

    for (int t0 = 0; t0 < T_; t0 += 16) {
        // stage x tile (coalesced; k==0 -> ones, k>=XK -> 0)
#pragma unroll
        for (int u = 0; u < 2; u++) {
            const int idx = tid + u * 512;
            const int tt = idx >> 6;
            const int kk = idx & 63;
            const int k  = kbase + kk;
            float xv = 0.f;
            if (k == 0)      xv = 1.f;
            else if (k < XK) xv = text[(size_t)(b * T_ + t0 + tt) * X_ + (k - 1)];
            xs[tt][kk] = xv;
        }
        // build av columns (pure LDS; 8 entries per thread)
#pragma unroll
        for (int u = 0; u < 8; u++) {
            const int tt = ttbase + 2 * u;
            const int t  = t0 + tt;
            av_s[tt][ijcol] = ijok ? a_s[t][ii] * v_s[t][jj] : 0.f;
        }
        __syncthreads();

#pragma unroll 4
        for (int tt = 0; tt < 16; tt++) {
            const float4 a0 = *(const float4*)&av_s[tt][tr * 4];
            const ulonglong2 x0 = *(const ulonglong2*)&xs[tt][tc * 4];
            const ulonglong2 x1 = *(const ulonglong2*)&xs[tt][tc * 4 + 32];
            const float aa[4] = {a0.x, a0.y, a0.z, a0.w};
#pragma unroll
            for (int i = 0; i < 4; i++) {
                const u64 ad = pack2(aa[i], aa[i]);
                fma2(acc[i][0], ad, x0.x);
                fma2(acc[i][1], ad, x0.y);
                fma2(acc[i][2], ad, x1.x);
                fma2(acc[i][3], ad, x1.y);
            }
        }
        __syncthreads();
    }

    // store 4 ij rows x 8 k (k groups at tc*4 and tc*4+32)
#pragma unroll
    for (int i = 0; i < 4; i++) {
        const int oij = ijbase + tr * 4 + i;
        if (oij >= IJ) continue;
        float* dst = g_fusion + (size_t)b * FDP + (size_t)oij * XK;
#pragma unroll
        for (int g = 0; g < 2; g++) {
            const int kb0 = kbase + tc * 4 + g * 32;
#pragma unroll
            for (int j = 0; j < 2; j++) {
                float lo, hi;
                unpack2(acc[i][g * 2 + j], lo, hi);
                const int k = kb0 + j * 2;
                if (k     < XK) dst[k]     = lo;
                if (k + 1 < XK) dst[k + 1] = hi;
            }
        }
    }
}

// ---------------------------------------------------------------------------
// Stage 2: split-K GEMM [128 x FDP] @ [FDP x 128] -> 296 partials.
// 256 threads; per-thread 8b x 8p (p split tc*4 / tc*4+64).
// Register prefetch of the next K-tile overlaps LDG with compute.
// ---------------------------------------------------------------------------
__global__ void __launch_bounds__(256, 2)
gemm_kernel(const float* __restrict__ W1)
{
    __shared__ __align__(16) float As[KT][132];  // [kk][b] 16.5 KB (528B rows)
    __shared__ __align__(16) float Bs[KT][128];  // [kk][p] 16 KB

    const int tid = threadIdx.x;
    const int tr  = tid >> 4;   // 0..15 -> b rows tr*8..+7
    const int tc  = tid & 15;   // 0..15 -> p cols {tc*4..+3, tc*4+64..+67}

    const int a_f4   = tid & 7;   // float4 index along f
    const int a_brow = tid >> 3;  // 0..31
    const int b_p4   = tid & 31;
    const int b_kk   = tid >> 5;  // 0..7

    u64 acc[8][4];
#pragma unroll
    for (int i = 0; i < 8; i++)
#pragma unroll
        for (int j = 0; j < 4; j++) acc[i][j] = 0ull;

    float4 pa[4], pb[4];

    // prologue: fetch first tile
    int tile = blockIdx.x;
    {
        const int kb = tile * KT;
#pragma unroll
        for (int u = 0; u < 4; u++)
            pa[u] = *(const float4*)(g_fusion +
                     (size_t)(a_brow + u * 32) * FDP + kb + a_f4 * 4);
#pragma unroll
        for (int u = 0; u < 4; u++) {
            const int f = kb + b_kk + u * 8;
            pb[u] = (f < FD) ? *(const float4*)(W1 + (size_t)f * PF + b_p4 * 4)
                             : make_float4(0.f, 0.f, 0.f, 0.f);
        }
    }
#pragma unroll
    for (int u = 0; u < 4; u++) {
        As[a_f4 * 4 + 0][a_brow + u * 32] = pa[u].x;
        As[a_f4 * 4 + 1][a_brow + u * 32] = pa[u].y;
        As[a_f4 * 4 + 2][a_brow + u * 32] = pa[u].z;
        As[a_f4 * 4 + 3][a_brow + u * 32] = pa[u].w;
        *(float4*)&Bs[b_kk + u * 8][b_p4 * 4] = pb[u];
    }
    __syncthreads();

    while (true) {
        const int next = tile + NSPLIT;
        const bool has = (next < NTILES);
        if (has) {
            const int kb = next * KT;
#pragma unroll
            for (int u = 0; u < 4; u++)
                pa[u] = *(const float4*)(g_fusion +
                         (size_t)(a_brow + u * 32) * FDP + kb + a_f4 * 4);
#pragma unroll
            for (int u = 0; u < 4; u++) {
                const int f = kb + b_kk + u * 8;
                pb[u] = (f < FD) ? *(const float4*)(W1 + (size_t)f * PF + b_p4 * 4)
                                 : make_float4(0.f, 0.f, 0.f, 0.f);
            }
        }

#pragma unroll 4
        for (int kk = 0; kk < KT; kk++) {
            const float4 a0 = *(const float4*)&As[kk][tr * 8];
            const float4 a1 = *(const float4*)&As[kk][tr * 8 + 4];
            const ulonglong2 q0 = *(const ulonglong2*)&Bs[kk][tc * 4];
            const ulonglong2 q1 = *(const ulonglong2*)&Bs[kk][tc * 4 + 64];
            const float aa[8] = {a0.x, a0.y, a0.z, a0.w, a1.x, a1.y, a1.z, a1.w};
#pragma unroll
            for (int i = 0; i < 8; i++) {
                const u64 ad = pack2(aa[i], aa[i]);
                fma2(acc[i][0], ad, q0.x);
                fma2(acc[i][1], ad, q0.y);
                fma2(acc[i][2], ad, q1.x);
                fma2(acc[i][3], ad, q1.y);
            }
        }

        if (!has) break;
        __syncthreads();
#pragma unroll
        for (int u = 0; u < 4; u++) {
            As[a_f4 * 4 + 0][a_brow + u * 32] = pa[u].x;
            As[a_f4 * 4 + 1][a_brow + u * 32] = pa[u].y;
            As[a_f4 * 4 + 2][a_brow + u * 32] = pa[u].z;
            As[a_f4 * 4 + 3][a_brow + u * 32] = pa[u].w;
            *(float4*)&Bs[b_kk + u * 8][b_p4 * 4] = pb[u];
        }
        __syncthreads();
        tile = next;
    }

    // deterministic partial store (p split tc*4 / tc*4+64)
    float* base = g_part + (size_t)blockIdx.x * B_ * PF;
#pragma unroll
    for (int i = 0; i < 8; i++) {
        const int b = tr * 8 + i;
        float* row = base + (size_t)b * PF;
        *(ulonglong2*)(row + tc * 4)      = make_ulonglong2(acc[i][0], acc[i][1]);
        *(ulonglong2*)(row + tc * 4 + 64) = make_ulonglong2(acc[i][2], acc[i][3]);
    }
}

// ---------------------------------------------------------------------------
// Stage 3: reduce partials -> h1 (relu) -> h2 (relu) -> sigmoid*6-3.
// ---------------------------------------------------------------------------
__global__ void __launch_bounds__(128)
mlp_kernel(const float* __restrict__ b1,
           const float* __restrict__ W2,
           const float* __restrict__ b2,
           const float* __restrict__ W3,
           const float* __restrict__ b3,
           float* __restrict__ out)
{
    __shared__ float h1[128];
    __shared__ float red[128];
    const int b = blockIdx.x;
    const int p = threadIdx.x;

    float s = b1[p];
    const float* pp = g_part + (size_t)b * PF + p;
#pragma unroll 8
    for (int c = 0; c < NSPLIT; c++) s += pp[(size_t)c * B_ * PF];
    h1[p] = fmaxf(s, 0.f);
    __syncthreads();

    float s2 = b2[p];
#pragma unroll 8
    for (int q = 0; q < PF; q++) s2 = fmaf(h1[q], W2[q * PF + p], s2);
    const float h2 = fmaxf(s2, 0.f);

    red[p] = h2 * W3[p];
    __syncthreads();
    for (int st = 64; st > 0; st >>= 1) {
        if (p < st) red[p] += red[p + st];
        __syncthreads();
    }
    if (p == 0) {
        const float z = red[0] + b3[0];
        out[b] = 6.f / (1.f + expf(-z)) - 3.f;
    }
}

// ---------------------------------------------------------------------------
extern "C" void kernel_launch(void* const* d_in, const int* in_sizes, int n_in,
                              void* d_out, int out_size)
{
    const float* audio = (const float*)d_in[0];
    const float* video = (const float*)d_in[1];
    const float* text  = (const float*)d_in[2];
    const float* W1    = (const float*)d_in[3];
    const float* b1    = (const float*)d_in[4];
    const float* W2    = (const float*)d_in[5];
    const float* b2    = (const float*)d_in[6];
    const float* W3    = (const float*)d_in[7];
    const float* b3    = (const float*)d_in[8];

    fusion_kernel<<<dim3((IJ + 255) / 256, 2, B_), 512>>>(audio, video, text);
    gemm_kernel<<<NSPLIT, 256>>>(W1);
    mlp_kernel<<<B_, 128>>>(b1, W2, b2, W3, b3, (float*)d_out);
}

// round 11
// speedup vs baseline: 2.4829x; 1.3716x over previous
#include <cuda_runtime.h>
#include <cuda_bf16.h>
#include <cstdint>

// ---------------------------------------------------------------------------
// T2FN: fusion = sum_t (a1 ⊗ v1 ⊗ x1)  [B, 49*49*97], then 3-layer MLP.
// Stage 1 (fusion): FFMA2 kernel (unchanged R9 winner), fp32, rows padded.
// Stage 2 (gemm_mma): split-K GEMM on mma.sync.m16n8k16 (bf16, fp32 acc).
//   3-pass bf16 hi/lo split for fp32-grade accuracy. 592 CTAs = 296 K-slices
//   x 2 p-halves; CTA tile 128b x 64p; warp tile 32x32. No smem transposes:
//   A=[b][f] + ldmatrix.x4, B=[f][p] + ldmatrix.x4.trans; row pads keep every
//   ldmatrix 16B-aligned and bank-conflict-free. Register prefetch of the
//   next K-tile.
// Stage 3 (mlp): reduce partials + bias/relu chain + sigmoid*6-3.
// NOTE: tcgen05 is NOT available (harness compiles PTX for compute_103, not
// 103a) — tensor work must go through mma.sync fallback HMMA.
// ---------------------------------------------------------------------------

typedef unsigned long long u64;

constexpr int B_  = 128;
constexpr int T_  = 64;
constexpr int A_  = 48;
constexpr int V_  = 48;
constexpr int X_  = 96;
constexpr int AI  = A_ + 1;      // 49
constexpr int VJ  = V_ + 1;      // 49
constexpr int XK  = X_ + 1;      // 97
constexpr int IJ  = AI * VJ;     // 2401
constexpr int FD  = IJ * XK;     // 232897
constexpr int FDP2 = 232960;     // FD padded to multiple of 64
constexpr int PF  = 128;
constexpr int NSPLIT = 296;      // K-slices
constexpr int KT  = 32;          // GEMM K-tile
constexpr int NT32 = FDP2 / KT;  // 7280

__device__ float g_fusion[(size_t)B_ * FDP2];        // ~119 MB (pad stays 0)
__device__ float g_part[(size_t)NSPLIT * B_ * PF];   // ~19.4 MB

__device__ __forceinline__ u64 pack2(float lo, float hi) {
    u64 r;
    asm("mov.b64 %0, {%1, %2};" : "=l"(r) : "f"(lo), "f"(hi));
    return r;
}
__device__ __forceinline__ void fma2(u64& acc, u64 a, u64 b) {
    asm("fma.rn.f32x2 %0, %1, %2, %0;" : "+l"(acc) : "l"(a), "l"(b));
}
__device__ __forceinline__ void unpack2(u64 v, float& lo, float& hi) {
    lo = __uint_as_float((unsigned)(v & 0xffffffffull));
    hi = __uint_as_float((unsigned)(v >> 32));
}

// ---------------------------------------------------------------------------
// Stage 1: fusion formation (unchanged R9 winner, stride FDP2).
// ---------------------------------------------------------------------------
__global__ void __launch_bounds__(512, 2)
fusion_kernel(const float* __restrict__ audio,
              const float* __restrict__ video,
              const float* __restrict__ text)
{
    __shared__ float a_s[T_][AI];
    __shared__ float v_s[T_][VJ];
    __shared__ __align__(16) float xs[16][64];
    __shared__ __align__(16) float av_s[16][260];

    const int b      = blockIdx.z;
    const int ijbase = blockIdx.x * 256;
    const int kbase  = blockIdx.y * 64;
    const int tid    = threadIdx.x;
    const int tr     = tid >> 3;
    const int tc     = tid & 7;

    if (tid < T_) { a_s[tid][0] = 1.f; v_s[tid][0] = 1.f; }
    {
        const float* ab = audio + (size_t)b * T_ * A_;
        const float* vb = video + (size_t)b * T_ * V_;
        for (int idx = tid; idx < T_ * A_; idx += 512) {
            const int t = idx / A_;
            const int c = idx - t * A_;
            a_s[t][c + 1] = ab[idx];
            v_s[t][c + 1] = vb[idx];
        }
    }

    const int  ijcol = tid & 255;
    const int  ttbase = tid >> 8;
    const int  ij   = ijbase + ijcol;
    const bool ijok = (ij < IJ);
    const int  ii   = ijok ? (ij / VJ) : 0;
    const int  jj   = ijok ? (ij - ii * VJ) : 0;

    u64 acc[4][4];
#pragma unroll
    for (int i = 0; i < 4; i++)
#pragma unroll
        for (int j = 0; j < 4; j++) acc[i][j] = 0ull;

    __syncthreads();

    for (int t0 = 0; t0 < T_; t0 += 16) {
#pragma unroll
        for (int u = 0; u < 2; u++) {
            const int idx = tid + u * 512;
            const int tt = idx >> 6;
            const int kk = idx & 63;
            const int k  = kbase + kk;
            float xv = 0.f;
            if (k == 0)      xv = 1.f;
            else if (k < XK) xv = text[(size_t)(b * T_ + t0 + tt) * X_ + (k - 1)];
            xs[tt][kk] = xv;
        }
#pragma unroll
        for (int u = 0; u < 8; u++) {
            const int tt = ttbase + 2 * u;
            const int t  = t0 + tt;
            av_s[tt][ijcol] = ijok ? a_s[t][ii] * v_s[t][jj] : 0.f;
        }
        __syncthreads();

#pragma unroll 4
        for (int tt = 0; tt < 16; tt++) {
            const float4 a0 = *(const float4*)&av_s[tt][tr * 4];
            const ulonglong2 x0 = *(const ulonglong2*)&xs[tt][tc * 4];
            const ulonglong2 x1 = *(const ulonglong2*)&xs[tt][tc * 4 + 32];
            const float aa[4] = {a0.x, a0.y, a0.z, a0.w};
#pragma unroll
            for (int i = 0; i < 4; i++) {
                const u64 ad = pack2(aa[i], aa[i]);
                fma2(acc[i][0], ad, x0.x);
                fma2(acc[i][1], ad, x0.y);
                fma2(acc[i][2], ad, x1.x);
                fma2(acc[i][3], ad, x1.y);
            }
        }
        __syncthreads();
    }

#pragma unroll
    for (int i = 0; i < 4; i++) {
        const int oij = ijbase + tr * 4 + i;
        if (oij >= IJ) continue;
        float* dst = g_fusion + (size_t)b * FDP2 + (size_t)oij * XK;
#pragma unroll
        for (int g = 0; g < 2; g++) {
            const int kb0 = kbase + tc * 4 + g * 32;
#pragma unroll
            for (int j = 0; j < 2; j++) {
                float lo, hi;
                unpack2(acc[i][g * 2 + j], lo, hi);
                const int k = kb0 + j * 2;
                if (k     < XK) dst[k]     = lo;
                if (k + 1 < XK) dst[k + 1] = hi;
            }
        }
    }
}

// ---------------------------------------------------------------------------
// Stage 2: mma.sync split-K GEMM.
// ---------------------------------------------------------------------------
__device__ __forceinline__ uint32_t smem_u32(const void* p) {
    uint32_t a;
    asm("{ .reg .u64 t; cvta.to.shared.u64 t, %1; cvt.u32.u64 %0, t; }"
        : "=r"(a) : "l"(p));
    return a;
}
__device__ __forceinline__ void ldsm_x4(uint32_t& r0, uint32_t& r1,
                                        uint32_t& r2, uint32_t& r3,
                                        uint32_t addr) {
    asm volatile("ldmatrix.sync.aligned.m8n8.x4.shared.b16 {%0,%1,%2,%3}, [%4];"
                 : "=r"(r0), "=r"(r1), "=r"(r2), "=r"(r3) : "r"(addr));
}
__device__ __forceinline__ void ldsm_x4t(uint32_t& r0, uint32_t& r1,
                                         uint32_t& r2, uint32_t& r3,
                                         uint32_t addr) {
    asm volatile("ldmatrix.sync.aligned.m8n8.x4.trans.shared.b16 {%0,%1,%2,%3}, [%4];"
                 : "=r"(r0), "=r"(r1), "=r"(r2), "=r"(r3) : "r"(addr));
}
__device__ __forceinline__ void mma16816(float* c, const uint32_t* a,
                                         const uint32_t* b) {
    asm volatile(
        "mma.sync.aligned.m16n8k16.row.col.f32.bf16.bf16.f32 "
        "{%0,%1,%2,%3}, {%4,%5,%6,%7}, {%8,%9}, {%0,%1,%2,%3};"
        : "+f"(c[0]), "+f"(c[1]), "+f"(c[2]), "+f"(c[3])
        : "r"(a[0]), "r"(a[1]), "r"(a[2]), "r"(a[3]), "r"(b[0]), "r"(b[1]));
}
__device__ __forceinline__ void split4(float4 v, uint2& hi, uint2& lo) {
    __nv_bfloat162 h01 = __float22bfloat162_rn(make_float2(v.x, v.y));
    __nv_bfloat162 h23 = __float22bfloat162_rn(make_float2(v.z, v.w));
    __nv_bfloat162 l01 = __float22bfloat162_rn(make_float2(
        v.x - __bfloat162float(h01.x), v.y - __bfloat162float(h01.y)));
    __nv_bfloat162 l23 = __float22bfloat162_rn(make_float2(
        v.z - __bfloat162float(h23.x), v.w - __bfloat162float(h23.y)));
    hi = make_uint2(*(uint32_t*)&h01, *(uint32_t*)&h23);
    lo = make_uint2(*(uint32_t*)&l01, *(uint32_t*)&l23);
}

constexpr int APAD = 56;   // A row stride in bf16 (112 B: 16B-aligned, 7 mod 8)
constexpr int BPAD = 72;   // B row stride in bf16 (144 B: 16B-aligned, 1 mod 8)

__global__ void __launch_bounds__(256, 2)
gemm_mma(const float* __restrict__ W1)
{
    __shared__ __align__(16) __nv_bfloat16 Ahi[128][APAD]; // [b][f] 14 KB
    __shared__ __align__(16) __nv_bfloat16 Alo[128][APAD];
    __shared__ __align__(16) __nv_bfloat16 Bhi[KT][BPAD];  // [f][p] 4.5 KB
    __shared__ __align__(16) __nv_bfloat16 Blo[KT][BPAD];

    const int tid    = threadIdx.x;
    const int wid    = tid >> 5;
    const int lane   = tid & 31;
    const int kslice = blockIdx.x >> 1;
    const int phalf  = blockIdx.x & 1;
    const int warp_b = (wid >> 1) * 32;
    const int warp_p = (wid & 1) * 32;

    const uint32_t aHiB = smem_u32(&Ahi[0][0]);
    const uint32_t aLoB = smem_u32(&Alo[0][0]);
    const uint32_t bHiB = smem_u32(&Bhi[0][0]);
    const uint32_t bLoB = smem_u32(&Blo[0][0]);

    // ldmatrix lane addressing
    const int g   = lane >> 3;
    const int l8  = lane & 7;
    // A x4: m = (g&1)*8 + l8 ; k-halves offset = (g>>1)*8
    const int a_m  = (g & 1) * 8 + l8;
    const int a_ko = (g >> 1) * 8;
    // B x4.trans: f = (g&1)*8 + l8 ; p offset = (g>>1)*8
    const int b_f  = (g & 1) * 8 + l8;
    const int b_po = (g >> 1) * 8;

    float acc[2][4][4];
#pragma unroll
    for (int m = 0; m < 2; m++)
#pragma unroll
        for (int n = 0; n < 4; n++)
#pragma unroll
            for (int j = 0; j < 4; j++) acc[m][n][j] = 0.f;

    // gmem load mapping
    const int a_b  = tid >> 3;         // + u*32
    const int a_f4 = tid & 7;
    const int b_fr = tid >> 4;         // + u*16
    const int b_p4 = tid & 15;

    float4 pa[4], pb[2];
    int tile = kslice;
    {
        const int kb = tile * KT;
#pragma unroll
        for (int u = 0; u < 4; u++)
            pa[u] = *(const float4*)(g_fusion +
                     (size_t)(a_b + u * 32) * FDP2 + kb + a_f4 * 4);
#pragma unroll
        for (int u = 0; u < 2; u++) {
            const int f = kb + b_fr + u * 16;
            pb[u] = (f < FD)
                ? *(const float4*)(W1 + (size_t)f * PF + phalf * 64 + b_p4 * 4)
                : make_float4(0.f, 0.f, 0.f, 0.f);
        }
    }
    // stage first tile
#pragma unroll
    for (int u = 0; u < 4; u++) {
        uint2 hi, lo;
        split4(pa[u], hi, lo);
        *(uint2*)&Ahi[a_b + u * 32][a_f4 * 4] = hi;
        *(uint2*)&Alo[a_b + u * 32][a_f4 * 4] = lo;
    }
#pragma unroll
    for (int u = 0; u < 2; u++) {
        uint2 hi, lo;
        split4(pb[u], hi, lo);
        *(uint2*)&Bhi[b_fr + u * 16][b_p4 * 4] = hi;
        *(uint2*)&Blo[b_fr + u * 16][b_p4 * 4] = lo;
    }
    __syncthreads();

    while (true) {
        const int next = tile + NSPLIT;
        const bool has = (next < NT32);
        if (has) {
            const int kb = next * KT;
#pragma unroll
            for (int u = 0; u < 4; u++)
                pa[u] = *(const float4*)(g_fusion +
                         (size_t)(a_b + u * 32) * FDP2 + kb + a_f4 * 4);
#pragma unroll
            for (int u = 0; u < 2; u++) {
                const int f = kb + b_fr + u * 16;
                pb[u] = (f < FD)
                    ? *(const float4*)(W1 + (size_t)f * PF + phalf * 64 + b_p4 * 4)
                    : make_float4(0.f, 0.f, 0.f, 0.f);
            }
        }

        // compute: 2 k16 steps x (2 m-tiles x 4 n-tiles) x 3 passes
#pragma unroll
        for (int ks = 0; ks < 2; ks++) {
            uint32_t fahi[2][4], falo[2][4];
#pragma unroll
            for (int m = 0; m < 2; m++) {
                const uint32_t off =
                    (uint32_t)((warp_b + m * 16 + a_m) * (APAD * 2)
                               + ks * 32 + a_ko * 2);
                ldsm_x4(fahi[m][0], fahi[m][1], fahi[m][2], fahi[m][3],
                        aHiB + off);
                ldsm_x4(falo[m][0], falo[m][1], falo[m][2], falo[m][3],
                        aLoB + off);
            }
            uint32_t fbhi[4][2], fblo[4][2];
#pragma unroll
            for (int np = 0; np < 2; np++) {   // n-tile pairs
                const uint32_t off =
                    (uint32_t)((ks * 16 + b_f) * (BPAD * 2)
                               + (warp_p + np * 16 + b_po) * 2);
                uint32_t r0, r1, r2, r3;
                ldsm_x4t(r0, r1, r2, r3, bHiB + off);
                fbhi[np * 2][0] = r0; fbhi[np * 2][1] = r1;
                fbhi[np * 2 + 1][0] = r2; fbhi[np * 2 + 1][1] = r3;
                ldsm_x4t(r0, r1, r2, r3, bLoB + off);
                fblo[np * 2][0] = r0; fblo[np * 2][1] = r1;
                fblo[np * 2 + 1][0] = r2; fblo[np * 2 + 1][1] = r3;
            }
#pragma unroll
            for (int m = 0; m < 2; m++)
#pragma unroll
                for (int n = 0; n < 4; n++) {
                    mma16816(acc[m][n], fahi[m], fbhi[n]);
                    mma16816(acc[m][n], fahi[m], fblo[n]);
                    mma16816(acc[m][n], falo[m], fbhi[n]);
                }
        }

        if (!has) break;
        __syncthreads();
#pragma unroll
        for (int u = 0; u < 4; u++) {
            uint2 hi, lo;
            split4(pa[u], hi, lo);
            *(uint2*)&Ahi[a_b + u * 32][a_f4 * 4] = hi;
            *(uint2*)&Alo[a_b + u * 32][a_f4 * 4] = lo;
        }
#pragma unroll
        for (int u = 0; u < 2; u++) {
            uint2 hi, lo;
            split4(pb[u], hi, lo);
            *(uint2*)&Bhi[b_fr + u * 16][b_p4 * 4] = hi;
            *(uint2*)&Blo[b_fr + u * 16][b_p4 * 4] = lo;
        }
        __syncthreads();
        tile = next;
    }

    // deterministic partial store
    float* base = g_part + (size_t)kslice * (B_ * PF) + phalf * 64;
#pragma unroll
    for (int m = 0; m < 2; m++) {
        const int b0 = warp_b + m * 16 + (lane >> 2);
#pragma unroll
        for (int n = 0; n < 4; n++) {
            const int p = warp_p + n * 8 + 2 * (lane & 3);
            *(float2*)(base + (size_t)b0 * PF + p) =
                make_float2(acc[m][n][0], acc[m][n][1]);
            *(float2*)(base + (size_t)(b0 + 8) * PF + p) =
                make_float2(acc[m][n][2], acc[m][n][3]);
        }
    }
}

// ---------------------------------------------------------------------------
// Stage 3: reduce partials -> h1 (relu) -> h2 (relu) -> sigmoid*6-3.
// ---------------------------------------------------------------------------
__global__ void __launch_bounds__(128)
mlp_kernel(const float* __restrict__ b1,
           const float* __restrict__ W2,
           const float* __restrict__ b2,
           const float* __restrict__ W3,
           const float* __restrict__ b3,
           float* __restrict__ out)
{
    __shared__ float h1[128];
    __shared__ float red[128];
    const int b = blockIdx.x;
    const int p = threadIdx.x;

    float s = b1[p];
    const float* pp = g_part + (size_t)b * PF + p;
#pragma unroll 8
    for (int c = 0; c < NSPLIT; c++) s += pp[(size_t)c * B_ * PF];
    h1[p] = fmaxf(s, 0.f);
    __syncthreads();

    float s2 = b2[p];
#pragma unroll 8
    for (int q = 0; q < PF; q++) s2 = fmaf(h1[q], W2[q * PF + p], s2);
    const float h2 = fmaxf(s2, 0.f);

    red[p] = h2 * W3[p];
    __syncthreads();
    for (int st = 64; st > 0; st >>= 1) {
        if (p < st) red[p] += red[p + st];
        __syncthreads();
    }
    if (p == 0) {
        const float z = red[0] + b3[0];
        out[b] = 6.f / (1.f + expf(-z)) - 3.f;
    }
}

// ---------------------------------------------------------------------------
extern "C" void kernel_launch(void* const* d_in, const int* in_sizes, int n_in,
                              void* d_out, int out_size)
{
    const float* audio = (const float*)d_in[0];
    const float* video = (const float*)d_in[1];
    const float* text  = (const float*)d_in[2];
    const float* W1    = (const float*)d_in[3];
    const float* b1    = (const float*)d_in[4];
    const float* W2    = (const float*)d_in[5];
    const float* b2    = (const float*)d_in[6];
    const float* W3    = (const float*)d_in[7];
    const float* b3    = (const float*)d_in[8];

    fusion_kernel<<<dim3((IJ + 255) / 256, 2, B_), 512>>>(audio, video, text);
    gemm_mma<<<2 * NSPLIT, 256>>>(W1);
    mlp_kernel<<<B_, 128>>>(b1, W2, b2, W3, b3, (float*)d_out);
}